// round 8
// baseline (speedup 1.0000x reference)
#include <cuda_runtime.h>
#include <cstdint>

#define FULL_MASK 0xffffffffu
typedef unsigned long long u64;

// ---------- packed f32x2 helpers (sm_100+ SIMD fp32, PTX-only) ----------
__device__ __forceinline__ u64 pk(float lo, float hi) {
    u64 r; asm("mov.b64 %0,{%1,%2};" : "=l"(r) : "f"(lo), "f"(hi)); return r;
}
__device__ __forceinline__ void unpk(u64 v, float& lo, float& hi) {
    asm("mov.b64 {%0,%1},%2;" : "=f"(lo), "=f"(hi) : "l"(v));
}
__device__ __forceinline__ u64 add2(u64 a, u64 b) {
    u64 d; asm("add.rn.f32x2 %0,%1,%2;" : "=l"(d) : "l"(a), "l"(b)); return d;
}
__device__ __forceinline__ u64 mul2(u64 a, u64 b) {
    u64 d; asm("mul.rn.f32x2 %0,%1,%2;" : "=l"(d) : "l"(a), "l"(b)); return d;
}
__device__ __forceinline__ u64 fma2(u64 a, u64 b, u64 c) {
    u64 d; asm("fma.rn.f32x2 %0,%1,%2,%3;" : "=l"(d) : "l"(a), "l"(b), "l"(c)); return d;
}
__device__ __forceinline__ u64 abs2(u64 a) {   // clear both sign bits
    u64 d; asm("and.b64 %0,%1,0x7FFFFFFF7FFFFFFF;" : "=l"(d) : "l"(a)); return d;
}

// Problem geometry: (16, 1, 1024, 1024) fp32 pred/target, scalar fp32 out.
constexpr int W = 1024;
constexpr int H = 1024;
constexpr int PLANES = 16;

constexpr int OUTC   = 62;                 // valid outputs per 64-col warp strip
constexpr int STRIPS = 17;                 // 62*17 = 1054 >= 1024
constexpr int RY     = 32;                 // rows per warp band
constexpr int BANDS  = H / RY;             // 32
constexpr int TOTAL_WARPS = STRIPS * BANDS * PLANES;  // 8704
constexpr int WPB    = 8;                  // 256 threads per block
constexpr int NBLOCKS = TOTAL_WARPS / WPB; // 1088

// 81-scaled SSIM constants (window SUMS instead of means; 81^2 cancels)
constexpr float C1S = 81.0f * 0.0001f;
constexpr float C2S = 81.0f * 0.0009f;

__device__ float2   g_partials[NBLOCKS];
__device__ unsigned g_count = 0;

__global__ void __launch_bounds__(WPB * 32, 5)   // cap ~51 regs -> 5 CTAs/SM
loss_main(const float* __restrict__ pred, const float* __restrict__ targ,
          float* __restrict__ out)
{
    const int warp  = blockIdx.x * WPB + (threadIdx.x >> 5);
    const int lane  = threadIdx.x & 31;
    const int strip = warp % STRIPS;
    const int band  = (warp / STRIPS) % BANDS;
    const int plane = warp / (STRIPS * BANDS);

    const int x0  = strip * OUTC + 2 * lane;       // even -> 8B aligned
    const bool xin = (x0 < W);

    const float* __restrict__ pb = pred + (size_t)plane * (size_t)(W * H) + x0;
    const float* __restrict__ tb = targ + (size_t)plane * (size_t)(W * H) + x0;

    const int y0 = band * RY;

    // hoisted packed constants (warp-uniform)
    const u64 C1S2  = pk(C1S, C1S);
    const u64 C2S2  = pk(C2S, C2S);
    const u64 E182  = pk(18.0f, 18.0f);
    const u64 NINE2 = pk(9.0f, 9.0f);
    const u64 NEG12 = pk(-1.0f, -1.0f);

    const bool valid0 = ((lane > 0) || (strip == 0)) && (x0 < W);
    const bool valid1 = (lane < 31) && (x0 + 1 < W);
    const u64 MASK2 = pk(valid0 ? 1.0f : 0.0f, valid1 ? 1.0f : 0.0f);

    u64 ssim_acc = 0ull;
    u64 l1_acc   = 0ull;

    auto load_row = [&](int y, u64& p, u64& t) {
        p = 0ull; t = 0ull;
        if (xin && (unsigned)y < (unsigned)H) {
            p = *(const u64*)(pb + (size_t)y * W);
            t = *(const u64*)(tb + (size_t)y * W);
        }
    };

    // horizontal 3-sums (hp, ht, hqq=hpp+htt, hpt) + masked L1 for this row
    auto horiz = [&](u64 p64, u64 t64, u64 l1m, u64& hp, u64& ht, u64& hqq,
                     u64& hpt) {
        float px, py, tx, ty;
        unpk(p64, px, py);
        unpk(t64, tx, ty);
        float pL = __shfl_up_sync(FULL_MASK, py, 1);
        float tL = __shfl_up_sync(FULL_MASK, ty, 1);
        float pR = __shfl_down_sync(FULL_MASK, px, 1);
        float tR = __shfl_down_sync(FULL_MASK, tx, 1);
        if (lane == 0) { pL = 0.0f; tL = 0.0f; }   // image-left zero pad

        const float cp  = px + py;
        const float ct  = tx + ty;
        const float cqq = fmaf(px, px, py * py) + fmaf(tx, tx, ty * ty);
        const float cpt = fmaf(px, tx, py * ty);

        const u64 pLR = pk(pL, pR);
        const u64 tLR = pk(tL, tR);
        hp  = add2(pLR, pk(cp, cp));
        ht  = add2(tLR, pk(ct, ct));
        hqq = fma2(pLR, pLR, fma2(tLR, tLR, pk(cqq, cqq)));
        hpt = fma2(pLR, tLR, pk(cpt, cpt));

        // L1 term for this row (masked: zero for halo rows / invalid lanes)
        const u64 df = abs2(fma2(t64, NEG12, p64));
        l1_acc = fma2(df, l1m, l1_acc);
    };

    // ---- prologue ----
    u64 hp0, ht0, hqq0, hpt0;
    u64 hp1, ht1, hqq1, hpt1;
    {
        u64 pA, tA;
        load_row(y0 - 1, pA, tA);
        horiz(pA, tA, 0ull, hp0, ht0, hqq0, hpt0);        // halo row: no L1
        load_row(y0, pA, tA);
        horiz(pA, tA, MASK2, hp1, ht1, hqq1, hpt1);       // row y0: L1 counts
    }
    u64 rnxtP, rnxtT;
    load_row(y0 + 1, rnxtP, rnxtT);

    #pragma unroll 4
    for (int r = 0; r < RY; ++r) {
        // issue next-next row load first (consumed next iteration)
        u64 rfutP, rfutT;
        load_row(y0 + r + 2, rfutP, rfutT);

        // horiz on row y0+r+1 (loaded last iteration); its L1 counts unless
        // it's the bottom halo row y0+RY (r == RY-1)
        u64 hp2, ht2, hqq2, hpt2;
        const u64 l1m = (r < RY - 1) ? MASK2 : 0ull;
        horiz(rnxtP, rnxtT, l1m, hp2, ht2, hqq2, hpt2);

        // packed 3x3 window sums
        const u64 SP  = add2(add2(hp0,  hp1),  hp2);
        const u64 ST  = add2(add2(ht0,  ht1),  ht2);
        const u64 Sqq = add2(add2(hqq0, hqq1), hqq2);
        const u64 SPT = add2(add2(hpt0, hpt1), hpt2);

        // packed SSIM polynomial (81-scaled)
        const u64 A   = mul2(SP, ST);
        const u64 A2  = add2(A, A);                 // 2*A
        const u64 B   = mul2(SP, SP);
        const u64 Cq  = mul2(ST, ST);
        const u64 n1  = add2(A2, C1S2);
        const u64 n2  = fma2(E182, SPT, fma2(A2, NEG12, C2S2));
        const u64 BC  = add2(B, Cq);
        const u64 d1  = add2(BC, C1S2);
        const u64 d2  = fma2(BC, NEG12, fma2(NINE2, Sqq, C2S2));
        const u64 num = mul2(n1, n2);
        const u64 den = mul2(d1, d2);    // >= C1S*C2S > 0

        float nx, ny, dx, dy;
        unpk(num, nx, ny);
        unpk(den, dx, dy);
        const float r0 = __fdividef(nx, dx);
        const float r1 = __fdividef(ny, dy);

        // val = clamp(0.5 - 0.5*r, 0, 1)
        float v0 = fmaf(r0, -0.5f, 0.5f);
        float v1 = fmaf(r1, -0.5f, 0.5f);
        v0 = fminf(fmaxf(v0, 0.0f), 1.0f);
        v1 = fminf(fmaxf(v1, 0.0f), 1.0f);

        ssim_acc = fma2(pk(v0, v1), MASK2, ssim_acc);

        // rotate window + raw buffer
        hp0 = hp1; ht0 = ht1; hqq0 = hqq1; hpt0 = hpt1;
        hp1 = hp2; ht1 = ht2; hqq1 = hqq2; hpt1 = hpt2;
        rnxtP = rfutP; rnxtT = rfutT;
    }

    // fold packed pair -> scalars
    float s_lo, s_hi, l_lo, l_hi;
    unpk(ssim_acc, s_lo, s_hi);
    unpk(l1_acc,   l_lo, l_hi);
    float ssim_s = s_lo + s_hi;
    float l1_s   = l_lo + l_hi;

    // ---- warp reduce ----
    #pragma unroll
    for (int off = 16; off > 0; off >>= 1) {
        ssim_s += __shfl_down_sync(FULL_MASK, ssim_s, off);
        l1_s   += __shfl_down_sync(FULL_MASK, l1_s, off);
    }

    // ---- block reduce ----
    __shared__ float2 s_part[WPB];
    __shared__ bool   s_last;
    const int wid = threadIdx.x >> 5;
    if (lane == 0) s_part[wid] = make_float2(ssim_s, l1_s);
    __syncthreads();

    if (threadIdx.x == 0) {
        float ss = 0.0f, ll = 0.0f;
        #pragma unroll
        for (int i = 0; i < WPB; ++i) { ss += s_part[i].x; ll += s_part[i].y; }
        g_partials[blockIdx.x] = make_float2(ss, ll);
        __threadfence();
        const unsigned old = atomicAdd(&g_count, 1u);
        s_last = (old == (unsigned)(gridDim.x - 1));
    }
    __syncthreads();

    // ---- last block: deterministic final reduction ----
    if (s_last) {
        double ss = 0.0, ll = 0.0;
        for (int i = threadIdx.x; i < NBLOCKS; i += WPB * 32) {
            const float2 v = g_partials[i];
            ss += (double)v.x;
            ll += (double)v.y;
        }
        #pragma unroll
        for (int off = 16; off > 0; off >>= 1) {
            ss += __shfl_down_sync(FULL_MASK, ss, off);
            ll += __shfl_down_sync(FULL_MASK, ll, off);
        }
        __shared__ double s_ss[WPB];
        __shared__ double s_ll[WPB];
        if (lane == 0) { s_ss[wid] = ss; s_ll[wid] = ll; }
        __syncthreads();
        if (threadIdx.x == 0) {
            double tss = 0.0, tll = 0.0;
            #pragma unroll
            for (int i = 0; i < WPB; ++i) { tss += s_ss[i]; tll += s_ll[i]; }
            const double N = (double)PLANES * (double)W * (double)H;
            out[0] = (float)(0.85 * (tss / N) + 0.15 * (tll / N));
            g_count = 0;   // reset for next graph replay
        }
    }
}

extern "C" void kernel_launch(void* const* d_in, const int* in_sizes, int n_in,
                              void* d_out, int out_size)
{
    const float* pred = (const float*)d_in[0];
    const float* targ = (const float*)d_in[1];
    float* out = (float*)d_out;

    loss_main<<<NBLOCKS, WPB * 32>>>(pred, targ, out);
}

// round 9
// speedup vs baseline: 1.1321x; 1.1321x over previous
#include <cuda_runtime.h>
#include <cstdint>

#define FULL_MASK 0xffffffffu
typedef unsigned long long u64;

// ---------- packed f32x2 helpers (sm_100+ SIMD fp32, PTX-only) ----------
__device__ __forceinline__ u64 pk(float lo, float hi) {
    u64 r; asm("mov.b64 %0,{%1,%2};" : "=l"(r) : "f"(lo), "f"(hi)); return r;
}
__device__ __forceinline__ void unpk(u64 v, float& lo, float& hi) {
    asm("mov.b64 {%0,%1},%2;" : "=f"(lo), "=f"(hi) : "l"(v));
}
__device__ __forceinline__ u64 add2(u64 a, u64 b) {
    u64 d; asm("add.rn.f32x2 %0,%1,%2;" : "=l"(d) : "l"(a), "l"(b)); return d;
}
__device__ __forceinline__ u64 mul2(u64 a, u64 b) {
    u64 d; asm("mul.rn.f32x2 %0,%1,%2;" : "=l"(d) : "l"(a), "l"(b)); return d;
}
__device__ __forceinline__ u64 fma2(u64 a, u64 b, u64 c) {
    u64 d; asm("fma.rn.f32x2 %0,%1,%2,%3;" : "=l"(d) : "l"(a), "l"(b), "l"(c)); return d;
}
__device__ __forceinline__ u64 abs2(u64 a) {   // clear both sign bits
    u64 d; asm("and.b64 %0,%1,0x7FFFFFFF7FFFFFFF;" : "=l"(d) : "l"(a)); return d;
}

// Problem geometry: (16, 1, 1024, 1024) fp32 pred/target, scalar fp32 out.
constexpr int W = 1024;
constexpr int H = 1024;
constexpr int PLANES = 16;

constexpr int OUTC   = 62;                 // valid outputs per 64-col warp strip
constexpr int STRIPS = 17;                 // 62*17 = 1054 >= 1024
constexpr int RY     = 32;                 // rows per warp band
constexpr int BANDS  = H / RY;             // 32
constexpr int TOTAL_WARPS = STRIPS * BANDS * PLANES;  // 8704
constexpr int WPB    = 8;                  // 256 threads per block
constexpr int NBLOCKS = TOTAL_WARPS / WPB; // 1088

// 81-scaled SSIM constants (window SUMS instead of means; 81^2 cancels)
constexpr float C1S = 81.0f * 0.0001f;
constexpr float C2S = 81.0f * 0.0009f;

__device__ float2   g_partials[NBLOCKS];
__device__ unsigned g_count = 0;

__global__ void __launch_bounds__(WPB * 32, 4)   // <=64 regs, no spill (R7-validated)
loss_main(const float* __restrict__ pred, const float* __restrict__ targ,
          float* __restrict__ out)
{
    const int warp  = blockIdx.x * WPB + (threadIdx.x >> 5);
    const int lane  = threadIdx.x & 31;
    const int strip = warp % STRIPS;
    const int band  = (warp / STRIPS) % BANDS;
    const int plane = warp / (STRIPS * BANDS);

    const int x0  = strip * OUTC + 2 * lane;       // even -> 8B aligned
    const bool xin = (x0 < W);

    const float* __restrict__ pb = pred + (size_t)plane * (size_t)(W * H) + x0;
    const float* __restrict__ tb = targ + (size_t)plane * (size_t)(W * H) + x0;

    const int y0 = band * RY;

    // hoisted packed constants (warp-uniform)
    const u64 C1S2  = pk(C1S, C1S);
    const u64 C2S2  = pk(C2S, C2S);
    const u64 E182  = pk(18.0f, 18.0f);
    const u64 NINE2 = pk(9.0f, 9.0f);
    const u64 NEG12 = pk(-1.0f, -1.0f);

    const bool valid0 = ((lane > 0) || (strip == 0)) && (x0 < W);
    const bool valid1 = (lane < 31) && (x0 + 1 < W);
    const u64 MASK2 = pk(valid0 ? 1.0f : 0.0f, valid1 ? 1.0f : 0.0f);

    u64 ssim_acc = 0ull;
    u64 l1_acc   = 0ull;

    auto load_row = [&](int y, u64& p, u64& t) {
        p = 0ull; t = 0ull;
        if (xin && (unsigned)y < (unsigned)H) {
            p = *(const u64*)(pb + (size_t)y * W);
            t = *(const u64*)(tb + (size_t)y * W);
        }
    };

    // horizontal 3-sums (hp, ht, hqq = hpp+htt, hpt) + masked L1 for this row
    auto horiz = [&](u64 p64, u64 t64, u64 l1m, u64& hp, u64& ht, u64& hqq,
                     u64& hpt) {
        float px, py, tx, ty;
        unpk(p64, px, py);
        unpk(t64, tx, ty);
        float pL = __shfl_up_sync(FULL_MASK, py, 1);
        float tL = __shfl_up_sync(FULL_MASK, ty, 1);
        float pR = __shfl_down_sync(FULL_MASK, px, 1);
        float tR = __shfl_down_sync(FULL_MASK, tx, 1);
        if (lane == 0) { pL = 0.0f; tL = 0.0f; }   // image-left zero pad

        const float cp  = px + py;
        const float ct  = tx + ty;
        const float cqq = fmaf(px, px, py * py) + fmaf(tx, tx, ty * ty);
        const float cpt = fmaf(px, tx, py * ty);

        const u64 pLR = pk(pL, pR);
        const u64 tLR = pk(tL, tR);
        hp  = add2(pLR, pk(cp, cp));
        ht  = add2(tLR, pk(ct, ct));
        hqq = fma2(pLR, pLR, fma2(tLR, tLR, pk(cqq, cqq)));
        hpt = fma2(pLR, tLR, pk(cpt, cpt));

        // L1 term for this row (masked: zero for halo rows / invalid lanes)
        const u64 df = abs2(fma2(t64, NEG12, p64));
        l1_acc = fma2(df, l1m, l1_acc);
    };

    // ---- prologue: fully build the 3-row window (rows y0-1, y0, y0+1) ----
    u64 hp0, ht0, hqq0, hpt0;
    u64 hp1, ht1, hqq1, hpt1;
    u64 hp2, ht2, hqq2, hpt2;
    {
        u64 pA, tA;
        load_row(y0 - 1, pA, tA);
        horiz(pA, tA, 0ull,  hp0, ht0, hqq0, hpt0);       // halo: no L1
        load_row(y0,     pA, tA);
        horiz(pA, tA, MASK2, hp1, ht1, hqq1, hpt1);       // row y0
        load_row(y0 + 1, pA, tA);
        horiz(pA, tA, MASK2, hp2, ht2, hqq2, hpt2);       // row y0+1
    }
    u64 rnxtP, rnxtT;
    load_row(y0 + 2, rnxtP, rnxtT);

    #pragma unroll 2
    for (int r = 0; r < RY; ++r) {
        // 1) issue far-ahead load (row y0+r+3), consumed next iteration's horiz
        u64 rfutP, rfutT;
        load_row(y0 + r + 3, rfutP, rfutT);

        // 2) SSIM poly on the COMPLETE window (rows y+r-1, y+r, y+r+1);
        //    hp2 etc. were computed last iteration -> no shfl on critical path
        const u64 SP  = add2(add2(hp0,  hp1),  hp2);
        const u64 ST  = add2(add2(ht0,  ht1),  ht2);
        const u64 Sqq = add2(add2(hqq0, hqq1), hqq2);
        const u64 SPT = add2(add2(hpt0, hpt1), hpt2);

        const u64 A   = mul2(SP, ST);
        const u64 A2  = add2(A, A);                 // 2*A
        const u64 B   = mul2(SP, SP);
        const u64 Cq  = mul2(ST, ST);
        const u64 n1  = add2(A2, C1S2);
        const u64 n2  = fma2(E182, SPT, fma2(A2, NEG12, C2S2));
        const u64 BC  = add2(B, Cq);
        const u64 d1  = add2(BC, C1S2);
        const u64 d2  = fma2(BC, NEG12, fma2(NINE2, Sqq, C2S2));
        const u64 num = mul2(n1, n2);
        const u64 den = mul2(d1, d2);    // >= C1S*C2S > 0

        float nx, ny, dx, dy;
        unpk(num, nx, ny);
        unpk(den, dx, dy);
        const float r0 = __fdividef(nx, dx);
        const float r1 = __fdividef(ny, dy);
        // ratio in [-1,1] exactly (AM-GM / Cauchy-Schwarz with C1,C2>0):
        // val = 0.5 - 0.5*ratio is already in [0,1]; reference clamp is a no-op.
        float v0 = fmaf(r0, -0.5f, 0.5f);
        float v1 = fmaf(r1, -0.5f, 0.5f);
        ssim_acc = fma2(pk(v0, v1), MASK2, ssim_acc);

        // 3) rotate window, then compute horiz of row y0+r+2 for NEXT iteration
        //    (its shuffles have a whole iteration to complete)
        hp0 = hp1; ht0 = ht1; hqq0 = hqq1; hpt0 = hpt1;
        hp1 = hp2; ht1 = ht2; hqq1 = hqq2; hpt1 = hpt2;

        // L1 mask: rows y0+2 .. y0+RY-1 count (r <= RY-3); y0+RY, y0+RY+1 are halo
        const u64 l1m = (r < RY - 2) ? MASK2 : 0ull;
        horiz(rnxtP, rnxtT, l1m, hp2, ht2, hqq2, hpt2);

        rnxtP = rfutP; rnxtT = rfutT;
    }

    // fold packed pair -> scalars
    float s_lo, s_hi, l_lo, l_hi;
    unpk(ssim_acc, s_lo, s_hi);
    unpk(l1_acc,   l_lo, l_hi);
    float ssim_s = s_lo + s_hi;
    float l1_s   = l_lo + l_hi;

    // ---- warp reduce ----
    #pragma unroll
    for (int off = 16; off > 0; off >>= 1) {
        ssim_s += __shfl_down_sync(FULL_MASK, ssim_s, off);
        l1_s   += __shfl_down_sync(FULL_MASK, l1_s, off);
    }

    // ---- block reduce ----
    __shared__ float2 s_part[WPB];
    __shared__ bool   s_last;
    const int wid = threadIdx.x >> 5;
    if (lane == 0) s_part[wid] = make_float2(ssim_s, l1_s);
    __syncthreads();

    if (threadIdx.x == 0) {
        float ss = 0.0f, ll = 0.0f;
        #pragma unroll
        for (int i = 0; i < WPB; ++i) { ss += s_part[i].x; ll += s_part[i].y; }
        g_partials[blockIdx.x] = make_float2(ss, ll);
        __threadfence();
        const unsigned old = atomicAdd(&g_count, 1u);
        s_last = (old == (unsigned)(gridDim.x - 1));
    }
    __syncthreads();

    // ---- last block: deterministic final reduction ----
    if (s_last) {
        double ss = 0.0, ll = 0.0;
        for (int i = threadIdx.x; i < NBLOCKS; i += WPB * 32) {
            const float2 v = g_partials[i];
            ss += (double)v.x;
            ll += (double)v.y;
        }
        #pragma unroll
        for (int off = 16; off > 0; off >>= 1) {
            ss += __shfl_down_sync(FULL_MASK, ss, off);
            ll += __shfl_down_sync(FULL_MASK, ll, off);
        }
        __shared__ double s_ss[WPB];
        __shared__ double s_ll[WPB];
        if (lane == 0) { s_ss[wid] = ss; s_ll[wid] = ll; }
        __syncthreads();
        if (threadIdx.x == 0) {
            double tss = 0.0, tll = 0.0;
            #pragma unroll
            for (int i = 0; i < WPB; ++i) { tss += s_ss[i]; tll += s_ll[i]; }
            const double N = (double)PLANES * (double)W * (double)H;
            out[0] = (float)(0.85 * (tss / N) + 0.15 * (tll / N));
            g_count = 0;   // reset for next graph replay
        }
    }
}

extern "C" void kernel_launch(void* const* d_in, const int* in_sizes, int n_in,
                              void* d_out, int out_size)
{
    const float* pred = (const float*)d_in[0];
    const float* targ = (const float*)d_in[1];
    float* out = (float*)d_out;

    loss_main<<<NBLOCKS, WPB * 32>>>(pred, targ, out);
}

// round 10
// speedup vs baseline: 1.2037x; 1.0633x over previous
#include <cuda_runtime.h>
#include <cstdint>

#define FULL_MASK 0xffffffffu
typedef unsigned long long u64;

// ---------- packed f32x2 helpers (sm_100+ SIMD fp32, PTX-only) ----------
__device__ __forceinline__ u64 pk(float lo, float hi) {
    u64 r; asm("mov.b64 %0,{%1,%2};" : "=l"(r) : "f"(lo), "f"(hi)); return r;
}
__device__ __forceinline__ void unpk(u64 v, float& lo, float& hi) {
    asm("mov.b64 {%0,%1},%2;" : "=f"(lo), "=f"(hi) : "l"(v));
}
__device__ __forceinline__ u64 add2(u64 a, u64 b) {
    u64 d; asm("add.rn.f32x2 %0,%1,%2;" : "=l"(d) : "l"(a), "l"(b)); return d;
}
__device__ __forceinline__ u64 mul2(u64 a, u64 b) {
    u64 d; asm("mul.rn.f32x2 %0,%1,%2;" : "=l"(d) : "l"(a), "l"(b)); return d;
}
__device__ __forceinline__ u64 fma2(u64 a, u64 b, u64 c) {
    u64 d; asm("fma.rn.f32x2 %0,%1,%2,%3;" : "=l"(d) : "l"(a), "l"(b), "l"(c)); return d;
}
__device__ __forceinline__ u64 abs2(u64 a) {   // clear both sign bits
    u64 d; asm("and.b64 %0,%1,0x7FFFFFFF7FFFFFFF;" : "=l"(d) : "l"(a)); return d;
}

// Problem geometry: (16, 1, 1024, 1024) fp32 pred/target, scalar fp32 out.
constexpr int W = 1024;
constexpr int H = 1024;
constexpr int PLANES = 16;

constexpr int OUTC   = 62;                 // valid outputs per 64-col warp strip
constexpr int STRIPS = 17;                 // 62*17 = 1054 >= 1024
constexpr int RY     = 32;                 // rows per warp band
constexpr int BANDS  = H / RY;             // 32
constexpr int TOTAL_WARPS = STRIPS * BANDS * PLANES;  // 8704
constexpr int WPB    = 8;                  // 256 threads per block
constexpr int NBLOCKS = TOTAL_WARPS / WPB; // 1088

// 81-scaled SSIM constants (window SUMS instead of means; 81^2 cancels)
constexpr float C1S = 81.0f * 0.0001f;
constexpr float C2S = 81.0f * 0.0009f;

__device__ float2   g_partials[NBLOCKS];
__device__ unsigned g_count = 0;

__global__ void __launch_bounds__(WPB * 32, 4)   // <=64 regs, no spill
loss_main(const float* __restrict__ pred, const float* __restrict__ targ,
          float* __restrict__ out)
{
    const int warp  = blockIdx.x * WPB + (threadIdx.x >> 5);
    const int lane  = threadIdx.x & 31;
    const int strip = warp % STRIPS;
    const int band  = (warp / STRIPS) % BANDS;
    const int plane = warp / (STRIPS * BANDS);

    const int x0  = strip * OUTC + 2 * lane;       // even -> 8B aligned
    const bool xin = (x0 < W);

    const int y0 = band * RY;

    // band-base pointers: in-loop rows become base + const*W (imm offsets
    // after unrolling -> no per-iteration IMAD address chains)
    const float* __restrict__ pb0 =
        pred + (size_t)plane * (size_t)(W * H) + (size_t)y0 * W + x0;
    const float* __restrict__ tb0 =
        targ + (size_t)plane * (size_t)(W * H) + (size_t)y0 * W + x0;

    // hoisted packed constants (warp-uniform)
    const u64 C1S2  = pk(C1S, C1S);
    const u64 C2S2  = pk(C2S, C2S);
    const u64 E182  = pk(18.0f, 18.0f);
    const u64 NINE2 = pk(9.0f, 9.0f);
    const u64 NEG12 = pk(-1.0f, -1.0f);

    const bool valid0 = ((lane > 0) || (strip == 0)) && (x0 < W);
    const bool valid1 = (lane < 31) && (x0 + 1 < W);
    const u64 MASK2 = pk(valid0 ? 1.0f : 0.0f, valid1 ? 1.0f : 0.0f);

    u64 ssim_acc = 0ull;
    u64 l1_acc   = 0ull;

    // k is row offset relative to y0 (may be -1 .. RY+1)
    auto load_row = [&](int k, u64& p, u64& t) {
        p = 0ull; t = 0ull;
        if (xin && (unsigned)(y0 + k) < (unsigned)H) {
            p = *(const u64*)(pb0 + (ptrdiff_t)k * W);
            t = *(const u64*)(tb0 + (ptrdiff_t)k * W);
        }
    };

    // horizontal 3-sums (hp, ht, hqq = hpp+htt, hpt) + masked L1 for this row
    auto horiz = [&](u64 p64, u64 t64, u64 l1m, u64& hp, u64& ht, u64& hqq,
                     u64& hpt) {
        float px, py, tx, ty;
        unpk(p64, px, py);
        unpk(t64, tx, ty);
        float pL = __shfl_up_sync(FULL_MASK, py, 1);
        float tL = __shfl_up_sync(FULL_MASK, ty, 1);
        float pR = __shfl_down_sync(FULL_MASK, px, 1);
        float tR = __shfl_down_sync(FULL_MASK, tx, 1);
        if (lane == 0) { pL = 0.0f; tL = 0.0f; }   // image-left zero pad

        const float cp  = px + py;
        const float ct  = tx + ty;
        const float cqq = fmaf(px, px, py * py) + fmaf(tx, tx, ty * ty);
        const float cpt = fmaf(px, tx, py * ty);

        const u64 pLR = pk(pL, pR);
        const u64 tLR = pk(tL, tR);
        hp  = add2(pLR, pk(cp, cp));
        ht  = add2(tLR, pk(ct, ct));
        hqq = fma2(pLR, pLR, fma2(tLR, tLR, pk(cqq, cqq)));
        hpt = fma2(pLR, tLR, pk(cpt, cpt));

        // L1 term for this row (masked: zero for halo rows / invalid lanes)
        const u64 df = abs2(fma2(t64, NEG12, p64));
        l1_acc = fma2(df, l1m, l1_acc);
    };

    // ---- prologue: fully build the 3-row window (rows y0-1, y0, y0+1) ----
    u64 hp0, ht0, hqq0, hpt0;
    u64 hp1, ht1, hqq1, hpt1;
    u64 hp2, ht2, hqq2, hpt2;
    {
        u64 pA, tA;
        load_row(-1, pA, tA);
        horiz(pA, tA, 0ull,  hp0, ht0, hqq0, hpt0);       // halo: no L1
        load_row(0, pA, tA);
        horiz(pA, tA, MASK2, hp1, ht1, hqq1, hpt1);       // row y0
        load_row(1, pA, tA);
        horiz(pA, tA, MASK2, hp2, ht2, hqq2, hpt2);       // row y0+1
    }
    u64 rnxtP, rnxtT;
    load_row(2, rnxtP, rnxtT);

    #pragma unroll 8
    for (int r = 0; r < RY; ++r) {
        // 1) issue far-ahead load (row y0+r+3), consumed next iteration's horiz
        u64 rfutP, rfutT;
        load_row(r + 3, rfutP, rfutT);

        // 2) SSIM poly on the COMPLETE window (rows y+r-1, y+r, y+r+1);
        //    hp2 etc. were computed last iteration -> no shfl on critical path
        const u64 SP  = add2(add2(hp0,  hp1),  hp2);
        const u64 ST  = add2(add2(ht0,  ht1),  ht2);
        const u64 Sqq = add2(add2(hqq0, hqq1), hqq2);
        const u64 SPT = add2(add2(hpt0, hpt1), hpt2);

        const u64 A   = mul2(SP, ST);
        const u64 A2  = add2(A, A);                 // 2*A
        const u64 B   = mul2(SP, SP);
        const u64 Cq  = mul2(ST, ST);
        const u64 n1  = add2(A2, C1S2);
        const u64 n2  = fma2(E182, SPT, fma2(A2, NEG12, C2S2));
        const u64 BC  = add2(B, Cq);
        const u64 d1  = add2(BC, C1S2);
        const u64 d2  = fma2(BC, NEG12, fma2(NINE2, Sqq, C2S2));
        const u64 num = mul2(n1, n2);
        const u64 den = mul2(d1, d2);    // >= C1S*C2S > 0

        float nx, ny, dx, dy;
        unpk(num, nx, ny);
        unpk(den, dx, dy);
        const float r0 = __fdividef(nx, dx);
        const float r1 = __fdividef(ny, dy);
        // ratio in [-1,1] exactly (AM-GM / Cauchy-Schwarz with C1,C2>0):
        // val = 0.5 - 0.5*ratio is already in [0,1]; reference clamp is a no-op.
        float v0 = fmaf(r0, -0.5f, 0.5f);
        float v1 = fmaf(r1, -0.5f, 0.5f);
        ssim_acc = fma2(pk(v0, v1), MASK2, ssim_acc);

        // 3) rotate window, then compute horiz of row y0+r+2 for NEXT iteration
        //    (its shuffles have a whole iteration to complete; unroll-8 lets
        //    ptxas rename these copies away)
        hp0 = hp1; ht0 = ht1; hqq0 = hqq1; hpt0 = hpt1;
        hp1 = hp2; ht1 = ht2; hqq1 = hqq2; hpt1 = hpt2;

        // L1 mask: rows y0+2 .. y0+RY-1 count (r <= RY-3); beyond = halo
        const u64 l1m = (r < RY - 2) ? MASK2 : 0ull;
        horiz(rnxtP, rnxtT, l1m, hp2, ht2, hqq2, hpt2);

        rnxtP = rfutP; rnxtT = rfutT;
    }

    // fold packed pair -> scalars
    float s_lo, s_hi, l_lo, l_hi;
    unpk(ssim_acc, s_lo, s_hi);
    unpk(l1_acc,   l_lo, l_hi);
    float ssim_s = s_lo + s_hi;
    float l1_s   = l_lo + l_hi;

    // ---- warp reduce ----
    #pragma unroll
    for (int off = 16; off > 0; off >>= 1) {
        ssim_s += __shfl_down_sync(FULL_MASK, ssim_s, off);
        l1_s   += __shfl_down_sync(FULL_MASK, l1_s, off);
    }

    // ---- block reduce ----
    __shared__ float2 s_part[WPB];
    __shared__ bool   s_last;
    const int wid = threadIdx.x >> 5;
    if (lane == 0) s_part[wid] = make_float2(ssim_s, l1_s);
    __syncthreads();

    if (threadIdx.x == 0) {
        float ss = 0.0f, ll = 0.0f;
        #pragma unroll
        for (int i = 0; i < WPB; ++i) { ss += s_part[i].x; ll += s_part[i].y; }
        g_partials[blockIdx.x] = make_float2(ss, ll);
        __threadfence();
        const unsigned old = atomicAdd(&g_count, 1u);
        s_last = (old == (unsigned)(gridDim.x - 1));
    }
    __syncthreads();

    // ---- last block: deterministic final reduction ----
    if (s_last) {
        double ss = 0.0, ll = 0.0;
        for (int i = threadIdx.x; i < NBLOCKS; i += WPB * 32) {
            const float2 v = g_partials[i];
            ss += (double)v.x;
            ll += (double)v.y;
        }
        #pragma unroll
        for (int off = 16; off > 0; off >>= 1) {
            ss += __shfl_down_sync(FULL_MASK, ss, off);
            ll += __shfl_down_sync(FULL_MASK, ll, off);
        }
        __shared__ double s_ss[WPB];
        __shared__ double s_ll[WPB];
        if (lane == 0) { s_ss[wid] = ss; s_ll[wid] = ll; }
        __syncthreads();
        if (threadIdx.x == 0) {
            double tss = 0.0, tll = 0.0;
            #pragma unroll
            for (int i = 0; i < WPB; ++i) { tss += s_ss[i]; tll += s_ll[i]; }
            const double N = (double)PLANES * (double)W * (double)H;
            out[0] = (float)(0.85 * (tss / N) + 0.15 * (tll / N));
            g_count = 0;   // reset for next graph replay
        }
    }
}

extern "C" void kernel_launch(void* const* d_in, const int* in_sizes, int n_in,
                              void* d_out, int out_size)
{
    const float* pred = (const float*)d_in[0];
    const float* targ = (const float*)d_in[1];
    float* out = (float*)d_out;

    loss_main<<<NBLOCKS, WPB * 32>>>(pred, targ, out);
}